// round 9
// baseline (speedup 1.0000x reference)
#include <cuda_runtime.h>

#define NPTS 2097152
#define NSTK 500
#define G    32
#define NC   (G*G*G)            // 32768 cells
#define WTASK 64                // points per warp-task
#define MAXT 81920
#define MAXL 192

using ull = unsigned long long;

// ---- packed f32x2 helpers (sm_103a) ----
__device__ __forceinline__ ull pk2(float lo, float hi) {
    ull r; asm("mov.b64 %0, {%1, %2};" : "=l"(r) : "f"(lo), "f"(hi)); return r;
}
__device__ __forceinline__ void up2(ull v, float& a, float& b) {
    asm("mov.b64 {%0, %1}, %2;" : "=f"(a), "=f"(b) : "l"(v));
}
__device__ __forceinline__ ull add2(ull a, ull b) {
    ull r; asm("add.rn.f32x2 %0, %1, %2;" : "=l"(r) : "l"(a), "l"(b)); return r;
}
__device__ __forceinline__ ull mul2(ull a, ull b) {
    ull r; asm("mul.rn.f32x2 %0, %1, %2;" : "=l"(r) : "l"(a), "l"(b)); return r;
}
__device__ __forceinline__ ull fma2(ull a, ull b, ull c) {
    ull r; asm("fma.rn.f32x2 %0, %1, %2, %3;" : "=l"(r) : "l"(a), "l"(b), "l"(c)); return r;
}
__device__ __forceinline__ float sqapx(float x) {
    float r; asm("sqrt.approx.f32 %0, %1;" : "=f"(r) : "f"(x)); return r;
}

#define ONE2   0x3f8000003f800000ull
#define NEG12  0xbf800000bf800000ull

// ---- scratch (device globals; zero-initialized at load) ----
__device__ float4      g_sorted[NPTS];       // wx,wy,wz, origidx-as-bits
__device__ int         g_hist[NC];           // INVARIANT: zero at entry to k_hist
__device__ int         g_cursor[NC];
__device__ int         g_cellCnt[NC];
__device__ float4      g_init4[NC];          // truncation init (d, r, g, b)
__device__ float       g_initw[NC];          // truncation init weight (0 or 1)
__device__ int         g_cellList[NC * MAXL];// contiguous per cell: [c*MAXL + j]
__device__ ulonglong2  g_spk[NSTK * 4];      // packed stroke params
__device__ int4        g_tasks[MAXT];
__device__ int         g_taskCount;
__device__ int         g_fetch;

__device__ __forceinline__ int cellOf(float x, float y, float z) {
    int ix = min(max(__float2int_rd((x + 1.0f) * 16.0f), 0), G - 1);
    int iy = min(max(__float2int_rd((y + 1.0f) * 16.0f), 0), G - 1);
    int iz = min(max(__float2int_rd((z + 1.0f) * 16.0f), 0), G - 1);
    return ix | (iy << 5) | (iz << 10);
}

__device__ __forceinline__ void warp_pt(float x, float y, float z,
                                        float& wx, float& wy, float& wz) {
    float n2 = fmaf(x, x, fmaf(y, y, z * z));
    float n  = fmaxf(sqrtf(n2), 1e-9f);
    float sc = 0.5f;
    if (n > 1.0f) sc = (2.0f - 1.0f / n) / n * 0.5f;
    wx = x * sc; wy = y * sc; wz = z * sc;
}

// ---------- L0: warp coords, emit coord output, histogram; reset task counters ----------
__global__ void __launch_bounds__(256)
k_hist(const float* __restrict__ coords, float* __restrict__ out) {
    const int t = blockIdx.x * blockDim.x + threadIdx.x;
    if (t == 0) { g_taskCount = 0; g_fetch = 0; }
    const float4* c4 = (const float4*)coords;
    float4 a = c4[3 * t + 0], b = c4[3 * t + 1], c = c4[3 * t + 2];
    float px[4] = { a.x, a.w, b.z, c.y };
    float py[4] = { a.y, b.x, b.w, c.z };
    float pz[4] = { a.z, b.y, c.x, c.w };
    float wxo[4], wyo[4], wzo[4];
#pragma unroll
    for (int i = 0; i < 4; i++) {
        warp_pt(px[i], py[i], pz[i], wxo[i], wyo[i], wzo[i]);
        atomicAdd(&g_hist[cellOf(wxo[i], wyo[i], wzo[i])], 1);
    }
    float4* o4 = (float4*)(out + 4 * NPTS);
    o4[3 * t + 0] = make_float4(wxo[0], wyo[0], wzo[0], wxo[1]);
    o4[3 * t + 1] = make_float4(wyo[1], wzo[1], wxo[2], wyo[2]);
    o4[3 * t + 2] = make_float4(wzo[2], wxo[3], wyo[3], wzo[3]);
}

// ---------- L1: scan over 32768 cells + warp-task building; re-zeros g_hist ----------
__global__ void __launch_bounds__(1024, 1)
k_scanTasks() {
    __shared__ int warpsum[32];
    int tid = threadIdx.x;
    int lane = tid & 31, wid = tid >> 5;
    int base = tid * 32;
    int v[32];
    int s = 0;
#pragma unroll
    for (int k = 0; k < 32; k++) { v[k] = g_hist[base + k]; s += v[k]; }
#pragma unroll
    for (int k = 0; k < 32; k++) g_hist[base + k] = 0;   // restore invariant
    int ps = s;
#pragma unroll
    for (int off = 1; off < 32; off <<= 1) {
        int t = __shfl_up_sync(0xffffffff, ps, off);
        if (lane >= off) ps += t;
    }
    if (lane == 31) warpsum[wid] = ps;
    __syncthreads();
    if (wid == 0) {
        int w = warpsum[lane];
        int pw = w;
#pragma unroll
        for (int off = 1; off < 32; off <<= 1) {
            int t = __shfl_up_sync(0xffffffff, pw, off);
            if (lane >= off) pw += t;
        }
        warpsum[lane] = pw - w;
    }
    __syncthreads();
    int o = warpsum[wid] + ps - s;
#pragma unroll
    for (int k = 0; k < 32; k++) {
        int c = base + k;
        g_cursor[c] = o;
        int np = v[k];
        if (np > 0) {
            int nt = (np + WTASK - 1) / WTASK;
            int b = atomicAdd(&g_taskCount, nt);
            for (int q = 0; q < nt; q++) {
                int a = o + q * WTASK;
                int e = min(o + np, a + WTASK);
                g_tasks[b + q] = make_int4(c, a, e, 0);
            }
        }
        o += np;
    }
}

// ---------- L2: recompute warp, scatter into cell-sorted order ----------
__global__ void __launch_bounds__(256)
k_scatter(const float* __restrict__ coords) {
    const int t = blockIdx.x * blockDim.x + threadIdx.x;
    const float4* c4 = (const float4*)coords;
    float4 a = c4[3 * t + 0], b = c4[3 * t + 1], c = c4[3 * t + 2];
    float px[4] = { a.x, a.w, b.z, c.y };
    float py[4] = { a.y, b.x, b.w, c.z };
    float pz[4] = { a.z, b.y, c.x, c.w };
#pragma unroll
    for (int i = 0; i < 4; i++) {
        float wx, wy, wz;
        warp_pt(px[i], py[i], pz[i], wx, wy, wz);
        int cc = cellOf(wx, wy, wz);
        int pos = atomicAdd(&g_cursor[cc], 1);
        g_sorted[pos] = make_float4(wx, wy, wz, __int_as_float(4 * t + i));
    }
}

// ---------- L3: pack strokes + per-cell cull + truncation (PROBED BY NCU) ----------
__global__ void __launch_bounds__(256)
k_cull(const float* __restrict__ shape,
       const float* __restrict__ color,
       const float* __restrict__ alpha) {
    int c = blockIdx.x * blockDim.x + threadIdx.x;   // one thread per cell
    if (c < NSTK) {
        int s = c;
        float cx = shape[4 * s + 0], cy = shape[4 * s + 1];
        float cz = shape[4 * s + 2], r = shape[4 * s + 3];
        float A  = fmaf(5.0f, r, 0.5f);
        float B2 = (A * 0.2f) * (A * 0.2f);
        float d  = fmaxf(alpha[s], 0.0f) * 50.0f;
        float cr = color[3 * s + 0], cg = color[3 * s + 1], cb = color[3 * s + 2];
        g_spk[4 * s + 0] = make_ulonglong2(pk2(-cx, -cx), pk2(-cy, -cy));
        g_spk[4 * s + 1] = make_ulonglong2(pk2(-cz, -cz), pk2(A, B2));
        g_spk[4 * s + 2] = make_ulonglong2(pk2(d, d),     pk2(cr, cr));
        g_spk[4 * s + 3] = make_ulonglong2(pk2(cg, cg),   pk2(cb, cb));
    }

    int ix = c & 31, iy = (c >> 5) & 31, iz = c >> 10;
    const float cs = 0.0625f;
    float lox = -1.0f + ix * cs, hix = lox + cs;
    float loy = -1.0f + iy * cs, hiy = loy + cs;
    float loz = -1.0f + iz * cs, hiz = loz + cs;
    int cnt = 0;
    int lastFull = -1;
    int* __restrict__ myList = &g_cellList[c * MAXL];
    for (int s = 0; s < NSTK; s++) {
        float4 sp = *(const float4*)&shape[4 * s];     // cx,cy,cz,r
        float R = sp.w + 0.1f + 1e-4f;
        float dx = fmaxf(fmaxf(lox - sp.x, sp.x - hix), 0.0f);
        float dy = fmaxf(fmaxf(loy - sp.y, sp.y - hiy), 0.0f);
        float dz = fmaxf(fmaxf(loz - sp.z, sp.z - hiz), 0.0f);
        float d2 = fmaf(dx, dx, fmaf(dy, dy, dz * dz));
        if (d2 < R * R) {
            float fx = fmaxf(sp.x - lox, hix - sp.x);
            float fy = fmaxf(sp.y - loy, hiy - sp.y);
            float fz = fmaxf(sp.z - loz, hiz - sp.z);
            float f2 = fmaf(fx, fx, fmaf(fy, fy, fz * fz));
            float Rin = sp.w - 0.1f - 1e-3f;
            if (Rin > 0.0f && f2 < Rin * Rin) {
                lastFull = s;
                cnt = 0;
            } else if (cnt < MAXL) {
                myList[cnt++] = s;
            }
        }
    }
    g_cellCnt[c] = cnt;
    if (lastFull >= 0) {
        int s = lastFull;
        g_init4[c] = make_float4(fmaxf(alpha[s], 0.0f) * 50.0f,
                                 color[3 * s + 0], color[3 * s + 1], color[3 * s + 2]);
        g_initw[c] = 0.0f;
    } else {
        g_init4[c] = make_float4(0.f, 0.f, 0.f, 0.f);
        g_initw[c] = 1.0f;
    }
}

// ---------- L4: persistent main blend, warp-granularity tasks ----------
__global__ void __launch_bounds__(256)
k_main(float* __restrict__ out) {
    const int lane = threadIdx.x & 31;
    const int nTasks = g_taskCount;

    for (;;) {
        int tkid;
        if (lane == 0) tkid = atomicAdd(&g_fetch, 1);
        tkid = __shfl_sync(0xffffffffu, tkid, 0);
        if (tkid >= nTasks) return;
        int4 tk = g_tasks[tkid];
        const int cell = tk.x, start = tk.y, end = tk.z;
        const int m = g_cellCnt[cell];
        const int* __restrict__ list = &g_cellList[cell * MAXL];

        const int q0 = start + lane * 2;
        const int q1 = q0 + 1;
        const bool ok0 = q0 < end, ok1 = q1 < end;
        float4 pa = ok0 ? g_sorted[q0] : make_float4(9.f, 9.f, 9.f, 0.f);
        float4 pb = ok1 ? g_sorted[q1] : make_float4(9.f, 9.f, 9.f, 0.f);

        ull cxx = pk2(pa.x, pb.x);
        ull cyy = pk2(pa.y, pb.y);
        ull czz = pk2(pa.z, pb.z);

        float4 iv = g_init4[cell];
        float  iw = g_initw[cell];
        ull hd = pk2(iv.x, iv.x);
        ull hr = pk2(iv.y, iv.y);
        ull hg = pk2(iv.z, iv.z);
        ull hb = pk2(iv.w, iv.w);
        ull hw = pk2(iw, iw);

#pragma unroll 2
        for (int j = 0; j < m; j++) {
            int s = list[j];
            const ulonglong2* __restrict__ sp = &g_spk[4 * s];
            ulonglong2 v0 = sp[0];
            ulonglong2 v1 = sp[1];
            float A, B2; up2(v1.y, A, B2);
            ull dx = add2(cxx, v0.x);
            ull dy = add2(cyy, v0.y);
            ull dz = add2(czz, v1.x);
            ull d2 = mul2(dx, dx);
            d2 = fma2(dy, dy, d2);
            d2 = fma2(dz, dz, d2);
            float qa, qb; up2(d2, qa, qb);
            bool act = (qa < B2) | (qb < B2);
            if (__ballot_sync(0xffffffffu, act)) {
                ulonglong2 v2 = sp[2];
                ulonglong2 v3 = sp[3];
                float t0 = __saturatef(fmaf(sqapx(qa), -5.0f, A));
                float t1 = __saturatef(fmaf(sqapx(qb), -5.0f, A));
                ull t2  = pk2(t0, t1);
                ull omt = fma2(t2, NEG12, ONE2);
                hd = fma2(t2, v2.x, mul2(omt, hd));
                hr = fma2(t2, v2.y, mul2(omt, hr));
                hg = fma2(t2, v3.x, mul2(omt, hg));
                hb = fma2(t2, v3.y, mul2(omt, hb));
                hw = mul2(omt, hw);
            }
        }

        float d0, d1, w0, w1, r0, r1, g0, g1, b0, b1;
        up2(hd, d0, d1);
        up2(hw, w0, w1);
        up2(hr, r0, r1);
        up2(hg, g0, g1);
        up2(hb, b0, b1);
        if (ok0) {
            int oi = __float_as_int(pa.w);
            float inv = 1.0f / (1.0f + 1e-6f - w0);
            out[oi] = d0;
            out[NPTS + 3 * oi + 0] = __saturatef(r0 * inv);
            out[NPTS + 3 * oi + 1] = __saturatef(g0 * inv);
            out[NPTS + 3 * oi + 2] = __saturatef(b0 * inv);
        }
        if (ok1) {
            int oi = __float_as_int(pb.w);
            float inv = 1.0f / (1.0f + 1e-6f - w1);
            out[oi] = d1;
            out[NPTS + 3 * oi + 0] = __saturatef(r1 * inv);
            out[NPTS + 3 * oi + 1] = __saturatef(g1 * inv);
            out[NPTS + 3 * oi + 2] = __saturatef(b1 * inv);
        }
    }
}

extern "C" void kernel_launch(void* const* d_in, const int* in_sizes, int n_in,
                              void* d_out, int out_size)
{
    const float* coords = (const float*)d_in[0];
    const float* shape  = (const float*)d_in[1];
    const float* color  = (const float*)d_in[2];
    const float* alpha  = (const float*)d_in[3];
    float* out = (float*)d_out;

    k_hist<<<NPTS / (4 * 256), 256>>>(coords, out);          // 0
    k_scanTasks<<<1, 1024>>>();                              // 1
    k_scatter<<<NPTS / (4 * 256), 256>>>(coords);            // 2
    k_cull<<<NC / 256, 256>>>(shape, color, alpha);          // 3 (ncu probe)
    k_main<<<592, 256>>>(out);                               // 4 (persistent)
}

// round 12
// speedup vs baseline: 1.1497x; 1.1497x over previous
#include <cuda_runtime.h>

#define NPTS 2097152
#define NSTK 500
#define G    32
#define NC   (G*G*G)            // 32768 cells
#define WTASK 64                // points per warp-task
#define MAXT 81920
#define MAXL 192

using ull = unsigned long long;

// ---- packed f32x2 helpers (sm_103a) ----
__device__ __forceinline__ ull pk2(float lo, float hi) {
    ull r; asm("mov.b64 %0, {%1, %2};" : "=l"(r) : "f"(lo), "f"(hi)); return r;
}
__device__ __forceinline__ void up2(ull v, float& a, float& b) {
    asm("mov.b64 {%0, %1}, %2;" : "=f"(a), "=f"(b) : "l"(v));
}
__device__ __forceinline__ ull add2(ull a, ull b) {
    ull r; asm("add.rn.f32x2 %0, %1, %2;" : "=l"(r) : "l"(a), "l"(b)); return r;
}
__device__ __forceinline__ ull mul2(ull a, ull b) {
    ull r; asm("mul.rn.f32x2 %0, %1, %2;" : "=l"(r) : "l"(a), "l"(b)); return r;
}
__device__ __forceinline__ ull fma2(ull a, ull b, ull c) {
    ull r; asm("fma.rn.f32x2 %0, %1, %2, %3;" : "=l"(r) : "l"(a), "l"(b), "l"(c)); return r;
}
__device__ __forceinline__ float sqapx(float x) {
    float r; asm("sqrt.approx.f32 %0, %1;" : "=f"(r) : "f"(x)); return r;
}

#define ONE2   0x3f8000003f800000ull
#define NEG12  0xbf800000bf800000ull

// ---- scratch (device globals; zero-initialized at load) ----
__device__ float4      g_sorted[NPTS];       // wx,wy,wz, origidx-as-bits
__device__ int         g_hist[NC];           // INVARIANT: zero at entry to k_hist
__device__ int         g_cursor[NC];
__device__ int         g_cellCnt[NC];
__device__ float4      g_init4[NC];          // truncation init (d, r, g, b)
__device__ float       g_initw[NC];          // truncation init weight (0 or 1)
__device__ int         g_cellList[NC * MAXL];// contiguous per cell: [c*MAXL + j]
__device__ ulonglong2  g_spk[NSTK * 4];      // packed stroke params
__device__ int4        g_tasks[MAXT];
__device__ int         g_taskCount;
__device__ int         g_fetch;

__device__ __forceinline__ int cellOf(float x, float y, float z) {
    int ix = min(max(__float2int_rd((x + 1.0f) * 16.0f), 0), G - 1);
    int iy = min(max(__float2int_rd((y + 1.0f) * 16.0f), 0), G - 1);
    int iz = min(max(__float2int_rd((z + 1.0f) * 16.0f), 0), G - 1);
    return ix | (iy << 5) | (iz << 10);
}

__device__ __forceinline__ void warp_pt(float x, float y, float z,
                                        float& wx, float& wy, float& wz) {
    float n2 = fmaf(x, x, fmaf(y, y, z * z));
    float n  = fmaxf(sqrtf(n2), 1e-9f);
    float sc = 0.5f;
    if (n > 1.0f) sc = (2.0f - 1.0f / n) / n * 0.5f;
    wx = x * sc; wy = y * sc; wz = z * sc;
}

// ---------- L0: warp coords, emit coord output, histogram; pack strokes ----------
__global__ void __launch_bounds__(256)
k_hist(const float* __restrict__ coords, float* __restrict__ out,
       const float* __restrict__ shape, const float* __restrict__ color,
       const float* __restrict__ alpha) {
    const int t = blockIdx.x * blockDim.x + threadIdx.x;
    if (t == 0) { g_taskCount = 0; g_fetch = 0; }
    if (t < NSTK) {
        int s = t;
        float cx = shape[4 * s + 0], cy = shape[4 * s + 1];
        float cz = shape[4 * s + 2], r = shape[4 * s + 3];
        float A  = fmaf(5.0f, r, 0.5f);
        float B2 = (A * 0.2f) * (A * 0.2f);
        float d  = fmaxf(alpha[s], 0.0f) * 50.0f;
        float cr = color[3 * s + 0], cg = color[3 * s + 1], cb = color[3 * s + 2];
        g_spk[4 * s + 0] = make_ulonglong2(pk2(-cx, -cx), pk2(-cy, -cy));
        g_spk[4 * s + 1] = make_ulonglong2(pk2(-cz, -cz), pk2(A, B2));
        g_spk[4 * s + 2] = make_ulonglong2(pk2(d, d),     pk2(cr, cr));
        g_spk[4 * s + 3] = make_ulonglong2(pk2(cg, cg),   pk2(cb, cb));
    }
    const float4* c4 = (const float4*)coords;
    float4 a = c4[3 * t + 0], b = c4[3 * t + 1], c = c4[3 * t + 2];
    float px[4] = { a.x, a.w, b.z, c.y };
    float py[4] = { a.y, b.x, b.w, c.z };
    float pz[4] = { a.z, b.y, c.x, c.w };
    float wxo[4], wyo[4], wzo[4];
#pragma unroll
    for (int i = 0; i < 4; i++) {
        warp_pt(px[i], py[i], pz[i], wxo[i], wyo[i], wzo[i]);
        atomicAdd(&g_hist[cellOf(wxo[i], wyo[i], wzo[i])], 1);
    }
    float4* o4 = (float4*)(out + 4 * NPTS);
    o4[3 * t + 0] = make_float4(wxo[0], wyo[0], wzo[0], wxo[1]);
    o4[3 * t + 1] = make_float4(wyo[1], wzo[1], wxo[2], wyo[2]);
    o4[3 * t + 2] = make_float4(wzo[2], wxo[3], wyo[3], wzo[3]);
}

// ---------- L1: scan over 32768 cells + warp-task building; re-zeros g_hist ----------
__global__ void __launch_bounds__(1024, 1)
k_scanTasks() {
    __shared__ int warpsum[32];
    int tid = threadIdx.x;
    int lane = tid & 31, wid = tid >> 5;
    int base = tid * 32;
    int v[32];
    int s = 0;
#pragma unroll
    for (int k = 0; k < 32; k++) { v[k] = g_hist[base + k]; s += v[k]; }
#pragma unroll
    for (int k = 0; k < 32; k++) g_hist[base + k] = 0;   // restore invariant
    int ps = s;
#pragma unroll
    for (int off = 1; off < 32; off <<= 1) {
        int t = __shfl_up_sync(0xffffffff, ps, off);
        if (lane >= off) ps += t;
    }
    if (lane == 31) warpsum[wid] = ps;
    __syncthreads();
    if (wid == 0) {
        int w = warpsum[lane];
        int pw = w;
#pragma unroll
        for (int off = 1; off < 32; off <<= 1) {
            int t = __shfl_up_sync(0xffffffff, pw, off);
            if (lane >= off) pw += t;
        }
        warpsum[lane] = pw - w;
    }
    __syncthreads();
    int o = warpsum[wid] + ps - s;
#pragma unroll
    for (int k = 0; k < 32; k++) {
        int c = base + k;
        g_cursor[c] = o;
        int np = v[k];
        if (np > 0) {
            int nt = (np + WTASK - 1) / WTASK;
            int b = atomicAdd(&g_taskCount, nt);
            for (int q = 0; q < nt; q++) {
                int a = o + q * WTASK;
                int e = min(o + np, a + WTASK);
                g_tasks[b + q] = make_int4(c, a, e, 0);
            }
        }
        o += np;
    }
}

// ---------- L2: recompute warp, scatter into cell-sorted order ----------
__global__ void __launch_bounds__(256)
k_scatter(const float* __restrict__ coords) {
    const int t = blockIdx.x * blockDim.x + threadIdx.x;
    const float4* c4 = (const float4*)coords;
    float4 a = c4[3 * t + 0], b = c4[3 * t + 1], c = c4[3 * t + 2];
    float px[4] = { a.x, a.w, b.z, c.y };
    float py[4] = { a.y, b.x, b.w, c.z };
    float pz[4] = { a.z, b.y, c.x, c.w };
#pragma unroll
    for (int i = 0; i < 4; i++) {
        float wx, wy, wz;
        warp_pt(px[i], py[i], pz[i], wx, wy, wz);
        int cc = cellOf(wx, wy, wz);
        int pos = atomicAdd(&g_cursor[cc], 1);
        g_sorted[pos] = make_float4(wx, wy, wz, __int_as_float(4 * t + i));
    }
}

// ---------- L3: warp-per-cell cull + truncation (ballot-parallel, order-exact) ----------
__global__ void __launch_bounds__(256)
k_cull(const float* __restrict__ shape,
       const float* __restrict__ color,
       const float* __restrict__ alpha) {
    const int c    = (blockIdx.x * blockDim.x + threadIdx.x) >> 5;  // one warp per cell
    const int lane = threadIdx.x & 31;

    int ix = c & 31, iy = (c >> 5) & 31, iz = c >> 10;
    const float cs = 0.0625f;
    float lox = -1.0f + ix * cs, hix = lox + cs;
    float loy = -1.0f + iy * cs, hiy = loy + cs;
    float loz = -1.0f + iz * cs, hiz = loz + cs;

    int cnt = 0;
    int lastFull = -1;
    int* __restrict__ myList = &g_cellList[c * MAXL];

    for (int base = 0; base < NSTK; base += 32) {
        int s = base + lane;
        bool hit = false, full = false;
        if (s < NSTK) {
            float4 sp = *(const float4*)&shape[4 * s];   // cx,cy,cz,r
            float R = sp.w + 0.1f + 1e-4f;
            float dx = fmaxf(fmaxf(lox - sp.x, sp.x - hix), 0.0f);
            float dy = fmaxf(fmaxf(loy - sp.y, sp.y - hiy), 0.0f);
            float dz = fmaxf(fmaxf(loz - sp.z, sp.z - hiz), 0.0f);
            float d2 = fmaf(dx, dx, fmaf(dy, dy, dz * dz));
            if (d2 < R * R) {
                hit = true;
                float fx = fmaxf(sp.x - lox, hix - sp.x);
                float fy = fmaxf(sp.y - loy, hiy - sp.y);
                float fz = fmaxf(sp.z - loz, hiz - sp.z);
                float f2 = fmaf(fx, fx, fmaf(fy, fy, fz * fz));
                float Rin = sp.w - 0.1f - 1e-3f;
                full = (Rin > 0.0f) && (f2 < Rin * Rin);
            }
        }
        unsigned hm = __ballot_sync(0xffffffffu, hit);
        unsigned fm = __ballot_sync(0xffffffffu, full);
        unsigned append = hm & ~fm;
        if (fm) {
            int f = 31 - __clz(fm);
            lastFull = base + f;
            cnt = 0;
            append &= (0xFFFFFFFEu << f);     // only lanes strictly after last full
        }
        if (append & (1u << lane)) {
            int pos = cnt + __popc(append & ((1u << lane) - 1));
            if (pos < MAXL) myList[pos] = s;
        }
        cnt = min(cnt + __popc(append), MAXL);
    }

    if (lane == 0) {
        g_cellCnt[c] = cnt;
        if (lastFull >= 0) {
            int s = lastFull;
            g_init4[c] = make_float4(fmaxf(alpha[s], 0.0f) * 50.0f,
                                     color[3 * s + 0], color[3 * s + 1], color[3 * s + 2]);
            g_initw[c] = 0.0f;
        } else {
            g_init4[c] = make_float4(0.f, 0.f, 0.f, 0.f);
            g_initw[c] = 1.0f;
        }
    }
}

// ---------- L4: persistent main blend (R8-measured config) ----------
__global__ void __launch_bounds__(128)
k_main(float* __restrict__ out) {
    const int lane = threadIdx.x & 31;
    const int nTasks = g_taskCount;

    for (;;) {
        int tkid;
        if (lane == 0) tkid = atomicAdd(&g_fetch, 1);
        tkid = __shfl_sync(0xffffffffu, tkid, 0);
        if (tkid >= nTasks) return;
        int4 tk = g_tasks[tkid];
        const int cell = tk.x, start = tk.y, end = tk.z;
        const int m = g_cellCnt[cell];
        const int* __restrict__ list = &g_cellList[cell * MAXL];

        const int q0 = start + lane * 2;
        const int q1 = q0 + 1;
        const bool ok0 = q0 < end, ok1 = q1 < end;
        float4 pa = ok0 ? g_sorted[q0] : make_float4(9.f, 9.f, 9.f, 0.f);
        float4 pb = ok1 ? g_sorted[q1] : make_float4(9.f, 9.f, 9.f, 0.f);

        ull cxx = pk2(pa.x, pb.x);
        ull cyy = pk2(pa.y, pb.y);
        ull czz = pk2(pa.z, pb.z);

        float4 iv = g_init4[cell];
        float  iw = g_initw[cell];
        ull hd = pk2(iv.x, iv.x);
        ull hr = pk2(iv.y, iv.y);
        ull hg = pk2(iv.z, iv.z);
        ull hb = pk2(iv.w, iv.w);
        ull hw = pk2(iw, iw);

        // software-pipelined: prefetch next stroke while blending current
        ulonglong2 v0, v1, v2, v3;
        if (m > 0) {
            int s = list[0];
            v0 = g_spk[4 * s + 0]; v1 = g_spk[4 * s + 1];
            v2 = g_spk[4 * s + 2]; v3 = g_spk[4 * s + 3];
        }
        for (int j = 0; j < m; j++) {
            ulonglong2 n0, n1, n2, n3;
            if (j + 1 < m) {
                int s = list[j + 1];
                n0 = g_spk[4 * s + 0]; n1 = g_spk[4 * s + 1];
                n2 = g_spk[4 * s + 2]; n3 = g_spk[4 * s + 3];
            }
            float A, B2; up2(v1.y, A, B2);
            ull dx = add2(cxx, v0.x);
            ull dy = add2(cyy, v0.y);
            ull dz = add2(czz, v1.x);
            ull d2 = mul2(dx, dx);
            d2 = fma2(dy, dy, d2);
            d2 = fma2(dz, dz, d2);
            float qa, qb; up2(d2, qa, qb);
            bool act = (qa < B2) | (qb < B2);
            if (__ballot_sync(0xffffffffu, act)) {
                float t0 = __saturatef(fmaf(sqapx(qa), -5.0f, A));
                float t1 = __saturatef(fmaf(sqapx(qb), -5.0f, A));
                ull t2  = pk2(t0, t1);
                ull omt = fma2(t2, NEG12, ONE2);
                hd = fma2(t2, v2.x, mul2(omt, hd));
                hr = fma2(t2, v2.y, mul2(omt, hr));
                hg = fma2(t2, v3.x, mul2(omt, hg));
                hb = fma2(t2, v3.y, mul2(omt, hb));
                hw = mul2(omt, hw);
            }
            v0 = n0; v1 = n1; v2 = n2; v3 = n3;
        }

        float d0, d1, w0, w1, r0, r1, g0, g1, b0, b1;
        up2(hd, d0, d1);
        up2(hw, w0, w1);
        up2(hr, r0, r1);
        up2(hg, g0, g1);
        up2(hb, b0, b1);
        if (ok0) {
            int oi = __float_as_int(pa.w);
            float inv = 1.0f / (1.0f + 1e-6f - w0);
            out[oi] = d0;
            out[NPTS + 3 * oi + 0] = __saturatef(r0 * inv);
            out[NPTS + 3 * oi + 1] = __saturatef(g0 * inv);
            out[NPTS + 3 * oi + 2] = __saturatef(b0 * inv);
        }
        if (ok1) {
            int oi = __float_as_int(pb.w);
            float inv = 1.0f / (1.0f + 1e-6f - w1);
            out[oi] = d1;
            out[NPTS + 3 * oi + 0] = __saturatef(r1 * inv);
            out[NPTS + 3 * oi + 1] = __saturatef(g1 * inv);
            out[NPTS + 3 * oi + 2] = __saturatef(b1 * inv);
        }
    }
}

extern "C" void kernel_launch(void* const* d_in, const int* in_sizes, int n_in,
                              void* d_out, int out_size)
{
    const float* coords = (const float*)d_in[0];
    const float* shape  = (const float*)d_in[1];
    const float* color  = (const float*)d_in[2];
    const float* alpha  = (const float*)d_in[3];
    float* out = (float*)d_out;

    k_hist<<<NPTS / (4 * 256), 256>>>(coords, out, shape, color, alpha);  // 0
    k_scanTasks<<<1, 1024>>>();                                           // 1
    k_scatter<<<NPTS / (4 * 256), 256>>>(coords);                         // 2
    k_cull<<<NC / 8, 256>>>(shape, color, alpha);                         // 3 (ncu probe)
    k_main<<<1184, 128>>>(out);                                           // 4 (persistent)
}

// round 13
// speedup vs baseline: 1.1573x; 1.0066x over previous
#include <cuda_runtime.h>

#define NPTS 2097152
#define NSTK 500
#define G    32
#define NC   (G*G*G)            // 32768 cells
#define WTASK 64                // points per warp-task
#define MAXT 81920
#define MAXL 192

using ull = unsigned long long;

// ---- packed f32x2 helpers (sm_103a) ----
__device__ __forceinline__ ull pk2(float lo, float hi) {
    ull r; asm("mov.b64 %0, {%1, %2};" : "=l"(r) : "f"(lo), "f"(hi)); return r;
}
__device__ __forceinline__ void up2(ull v, float& a, float& b) {
    asm("mov.b64 {%0, %1}, %2;" : "=f"(a), "=f"(b) : "l"(v));
}
__device__ __forceinline__ ull add2(ull a, ull b) {
    ull r; asm("add.rn.f32x2 %0, %1, %2;" : "=l"(r) : "l"(a), "l"(b)); return r;
}
__device__ __forceinline__ ull mul2(ull a, ull b) {
    ull r; asm("mul.rn.f32x2 %0, %1, %2;" : "=l"(r) : "l"(a), "l"(b)); return r;
}
__device__ __forceinline__ ull fma2(ull a, ull b, ull c) {
    ull r; asm("fma.rn.f32x2 %0, %1, %2, %3;" : "=l"(r) : "l"(a), "l"(b), "l"(c)); return r;
}
__device__ __forceinline__ float sqapx(float x) {
    float r; asm("sqrt.approx.f32 %0, %1;" : "=f"(r) : "f"(x)); return r;
}

#define ONE2   0x3f8000003f800000ull
#define NEG12  0xbf800000bf800000ull

// ---- scratch (device globals; zero-initialized at load) ----
__device__ float4      g_sorted[NPTS];       // wx,wy,wz, origidx-as-bits
__device__ unsigned    g_pack[NPTS];         // (cell<<17) | within-cell rank
__device__ int         g_hist[NC];           // INVARIANT: zero at entry to k_hist
__device__ int         g_off[NC];
__device__ int         g_cellCnt[NC];
__device__ float4      g_init4[NC];          // truncation init (d, r, g, b)
__device__ float       g_initw[NC];          // truncation init weight (0 or 1)
__device__ int         g_cellList[NC * MAXL];// contiguous per cell: [c*MAXL + j]
__device__ ulonglong2  g_spk[NSTK * 4];      // packed stroke params
__device__ int4        g_tasks[MAXT];
__device__ int         g_taskCount;
__device__ int         g_fetch;

__device__ __forceinline__ int cellOf(float x, float y, float z) {
    int ix = min(max(__float2int_rd((x + 1.0f) * 16.0f), 0), G - 1);
    int iy = min(max(__float2int_rd((y + 1.0f) * 16.0f), 0), G - 1);
    int iz = min(max(__float2int_rd((z + 1.0f) * 16.0f), 0), G - 1);
    return ix | (iy << 5) | (iz << 10);
}

__device__ __forceinline__ void warp_pt(float x, float y, float z,
                                        float& wx, float& wy, float& wz) {
    float n2 = fmaf(x, x, fmaf(y, y, z * z));
    float n  = fmaxf(sqrtf(n2), 1e-9f);
    float sc = 0.5f;
    if (n > 1.0f) sc = (2.0f - 1.0f / n) / n * 0.5f;
    wx = x * sc; wy = y * sc; wz = z * sc;
}

// ---------- L0: warp coords, emit coord output, histogram + rank; pack strokes ----------
__global__ void __launch_bounds__(256)
k_hist(const float* __restrict__ coords, float* __restrict__ out,
       const float* __restrict__ shape, const float* __restrict__ color,
       const float* __restrict__ alpha) {
    const int t = blockIdx.x * blockDim.x + threadIdx.x;
    if (t == 0) { g_taskCount = 0; g_fetch = 0; }
    if (t < NSTK) {
        int s = t;
        float cx = shape[4 * s + 0], cy = shape[4 * s + 1];
        float cz = shape[4 * s + 2], r = shape[4 * s + 3];
        float A  = fmaf(5.0f, r, 0.5f);
        float B2 = (A * 0.2f) * (A * 0.2f);
        float d  = fmaxf(alpha[s], 0.0f) * 50.0f;
        float cr = color[3 * s + 0], cg = color[3 * s + 1], cb = color[3 * s + 2];
        g_spk[4 * s + 0] = make_ulonglong2(pk2(-cx, -cx), pk2(-cy, -cy));
        g_spk[4 * s + 1] = make_ulonglong2(pk2(-cz, -cz), pk2(A, B2));
        g_spk[4 * s + 2] = make_ulonglong2(pk2(d, d),     pk2(cr, cr));
        g_spk[4 * s + 3] = make_ulonglong2(pk2(cg, cg),   pk2(cb, cb));
    }
    const float4* c4 = (const float4*)coords;
    float4 a = c4[3 * t + 0], b = c4[3 * t + 1], c = c4[3 * t + 2];
    float px[4] = { a.x, a.w, b.z, c.y };
    float py[4] = { a.y, b.x, b.w, c.z };
    float pz[4] = { a.z, b.y, c.x, c.w };
    float wxo[4], wyo[4], wzo[4];
#pragma unroll
    for (int i = 0; i < 4; i++) {
        warp_pt(px[i], py[i], pz[i], wxo[i], wyo[i], wzo[i]);
        int cc = cellOf(wxo[i], wyo[i], wzo[i]);
        unsigned rank = (unsigned)atomicAdd(&g_hist[cc], 1);
        g_pack[4 * t + i] = ((unsigned)cc << 17) | rank;
    }
    float4* o4 = (float4*)(out + 4 * NPTS);
    o4[3 * t + 0] = make_float4(wxo[0], wyo[0], wzo[0], wxo[1]);
    o4[3 * t + 1] = make_float4(wyo[1], wzo[1], wxo[2], wyo[2]);
    o4[3 * t + 2] = make_float4(wzo[2], wxo[3], wyo[3], wzo[3]);
}

// ---------- L1: scan over 32768 cells + warp-task building; re-zeros g_hist ----------
__global__ void __launch_bounds__(1024, 1)
k_scanTasks() {
    __shared__ int warpsum[32];
    int tid = threadIdx.x;
    int lane = tid & 31, wid = tid >> 5;
    int base = tid * 32;
    int v[32];
    int s = 0;
#pragma unroll
    for (int k = 0; k < 32; k++) { v[k] = g_hist[base + k]; s += v[k]; }
#pragma unroll
    for (int k = 0; k < 32; k++) g_hist[base + k] = 0;   // restore invariant
    int ps = s;
#pragma unroll
    for (int off = 1; off < 32; off <<= 1) {
        int t = __shfl_up_sync(0xffffffff, ps, off);
        if (lane >= off) ps += t;
    }
    if (lane == 31) warpsum[wid] = ps;
    __syncthreads();
    if (wid == 0) {
        int w = warpsum[lane];
        int pw = w;
#pragma unroll
        for (int off = 1; off < 32; off <<= 1) {
            int t = __shfl_up_sync(0xffffffff, pw, off);
            if (lane >= off) pw += t;
        }
        warpsum[lane] = pw - w;
    }
    __syncthreads();
    int o = warpsum[wid] + ps - s;
#pragma unroll
    for (int k = 0; k < 32; k++) {
        int c = base + k;
        g_off[c] = o;
        int np = v[k];
        if (np > 0) {
            int nt = (np + WTASK - 1) / WTASK;
            int b = atomicAdd(&g_taskCount, nt);
            for (int q = 0; q < nt; q++) {
                int a = o + q * WTASK;
                int e = min(o + np, a + WTASK);
                g_tasks[b + q] = make_int4(c, a, e, 0);
            }
        }
        o += np;
    }
}

// ---------- L2: recompute warp, scatter via precomputed rank (no atomics) ----------
__global__ void __launch_bounds__(256)
k_scatter(const float* __restrict__ coords) {
    const int t = blockIdx.x * blockDim.x + threadIdx.x;
    const float4* c4 = (const float4*)coords;
    float4 a = c4[3 * t + 0], b = c4[3 * t + 1], c = c4[3 * t + 2];
    float px[4] = { a.x, a.w, b.z, c.y };
    float py[4] = { a.y, b.x, b.w, c.z };
    float pz[4] = { a.z, b.y, c.x, c.w };
#pragma unroll
    for (int i = 0; i < 4; i++) {
        float wx, wy, wz;
        warp_pt(px[i], py[i], pz[i], wx, wy, wz);
        unsigned pk = g_pack[4 * t + i];
        int cc   = (int)(pk >> 17);
        int rank = (int)(pk & 0x1FFFFu);
        int pos  = g_off[cc] + rank;
        g_sorted[pos] = make_float4(wx, wy, wz, __int_as_float(4 * t + i));
    }
}

// ---------- L3: warp-per-cell cull + truncation (ballot-parallel, order-exact) ----------
__global__ void __launch_bounds__(256)
k_cull(const float* __restrict__ shape,
       const float* __restrict__ color,
       const float* __restrict__ alpha) {
    const int c    = (blockIdx.x * blockDim.x + threadIdx.x) >> 5;  // one warp per cell
    const int lane = threadIdx.x & 31;

    int ix = c & 31, iy = (c >> 5) & 31, iz = c >> 10;
    const float cs = 0.0625f;
    float lox = -1.0f + ix * cs, hix = lox + cs;
    float loy = -1.0f + iy * cs, hiy = loy + cs;
    float loz = -1.0f + iz * cs, hiz = loz + cs;

    int cnt = 0;
    int lastFull = -1;
    int* __restrict__ myList = &g_cellList[c * MAXL];

    for (int base = 0; base < NSTK; base += 32) {
        int s = base + lane;
        bool hit = false, full = false;
        if (s < NSTK) {
            float4 sp = *(const float4*)&shape[4 * s];   // cx,cy,cz,r
            float R = sp.w + 0.1f + 1e-4f;
            float dx = fmaxf(fmaxf(lox - sp.x, sp.x - hix), 0.0f);
            float dy = fmaxf(fmaxf(loy - sp.y, sp.y - hiy), 0.0f);
            float dz = fmaxf(fmaxf(loz - sp.z, sp.z - hiz), 0.0f);
            float d2 = fmaf(dx, dx, fmaf(dy, dy, dz * dz));
            if (d2 < R * R) {
                hit = true;
                float fx = fmaxf(sp.x - lox, hix - sp.x);
                float fy = fmaxf(sp.y - loy, hiy - sp.y);
                float fz = fmaxf(sp.z - loz, hiz - sp.z);
                float f2 = fmaf(fx, fx, fmaf(fy, fy, fz * fz));
                float Rin = sp.w - 0.1f - 1e-3f;
                full = (Rin > 0.0f) && (f2 < Rin * Rin);
            }
        }
        unsigned hm = __ballot_sync(0xffffffffu, hit);
        unsigned fm = __ballot_sync(0xffffffffu, full);
        unsigned append = hm & ~fm;
        if (fm) {
            int f = 31 - __clz(fm);
            lastFull = base + f;
            cnt = 0;
            append &= (0xFFFFFFFEu << f);     // only lanes strictly after last full
        }
        if (append & (1u << lane)) {
            int pos = cnt + __popc(append & ((1u << lane) - 1));
            if (pos < MAXL) myList[pos] = s;
        }
        cnt = min(cnt + __popc(append), MAXL);
    }

    if (lane == 0) {
        g_cellCnt[c] = cnt;
        if (lastFull >= 0) {
            int s = lastFull;
            g_init4[c] = make_float4(fmaxf(alpha[s], 0.0f) * 50.0f,
                                     color[3 * s + 0], color[3 * s + 1], color[3 * s + 2]);
            g_initw[c] = 0.0f;
        } else {
            g_init4[c] = make_float4(0.f, 0.f, 0.f, 0.f);
            g_initw[c] = 1.0f;
        }
    }
}

// ---------- L4: persistent main blend; force 8 blocks/SM for occupancy ----------
__global__ void __launch_bounds__(128, 8)
k_main(float* __restrict__ out) {
    const int lane = threadIdx.x & 31;
    const int nTasks = g_taskCount;

    for (;;) {
        int tkid;
        if (lane == 0) tkid = atomicAdd(&g_fetch, 1);
        tkid = __shfl_sync(0xffffffffu, tkid, 0);
        if (tkid >= nTasks) return;
        int4 tk = g_tasks[tkid];
        const int cell = tk.x, start = tk.y, end = tk.z;
        const int m = g_cellCnt[cell];
        const int* __restrict__ list = &g_cellList[cell * MAXL];

        const int q0 = start + lane * 2;
        const int q1 = q0 + 1;
        const bool ok0 = q0 < end, ok1 = q1 < end;
        float4 pa = ok0 ? g_sorted[q0] : make_float4(9.f, 9.f, 9.f, 0.f);
        float4 pb = ok1 ? g_sorted[q1] : make_float4(9.f, 9.f, 9.f, 0.f);

        ull cxx = pk2(pa.x, pb.x);
        ull cyy = pk2(pa.y, pb.y);
        ull czz = pk2(pa.z, pb.z);

        float4 iv = g_init4[cell];
        float  iw = g_initw[cell];
        ull hd = pk2(iv.x, iv.x);
        ull hr = pk2(iv.y, iv.y);
        ull hg = pk2(iv.z, iv.z);
        ull hb = pk2(iv.w, iv.w);
        ull hw = pk2(iw, iw);

        // software-pipelined: prefetch next stroke while blending current
        ulonglong2 v0, v1, v2, v3;
        if (m > 0) {
            int s = list[0];
            v0 = g_spk[4 * s + 0]; v1 = g_spk[4 * s + 1];
            v2 = g_spk[4 * s + 2]; v3 = g_spk[4 * s + 3];
        }
        for (int j = 0; j < m; j++) {
            ulonglong2 n0, n1, n2, n3;
            if (j + 1 < m) {
                int s = list[j + 1];
                n0 = g_spk[4 * s + 0]; n1 = g_spk[4 * s + 1];
                n2 = g_spk[4 * s + 2]; n3 = g_spk[4 * s + 3];
            }
            float A, B2; up2(v1.y, A, B2);
            ull dx = add2(cxx, v0.x);
            ull dy = add2(cyy, v0.y);
            ull dz = add2(czz, v1.x);
            ull d2 = mul2(dx, dx);
            d2 = fma2(dy, dy, d2);
            d2 = fma2(dz, dz, d2);
            float qa, qb; up2(d2, qa, qb);
            bool act = (qa < B2) | (qb < B2);
            if (__ballot_sync(0xffffffffu, act)) {
                float t0 = __saturatef(fmaf(sqapx(qa), -5.0f, A));
                float t1 = __saturatef(fmaf(sqapx(qb), -5.0f, A));
                ull t2  = pk2(t0, t1);
                ull omt = fma2(t2, NEG12, ONE2);
                hd = fma2(t2, v2.x, mul2(omt, hd));
                hr = fma2(t2, v2.y, mul2(omt, hr));
                hg = fma2(t2, v3.x, mul2(omt, hg));
                hb = fma2(t2, v3.y, mul2(omt, hb));
                hw = mul2(omt, hw);
            }
            v0 = n0; v1 = n1; v2 = n2; v3 = n3;
        }

        float d0, d1, w0, w1, r0, r1, g0, g1, b0, b1;
        up2(hd, d0, d1);
        up2(hw, w0, w1);
        up2(hr, r0, r1);
        up2(hg, g0, g1);
        up2(hb, b0, b1);
        if (ok0) {
            int oi = __float_as_int(pa.w);
            float inv = 1.0f / (1.0f + 1e-6f - w0);
            out[oi] = d0;
            out[NPTS + 3 * oi + 0] = __saturatef(r0 * inv);
            out[NPTS + 3 * oi + 1] = __saturatef(g0 * inv);
            out[NPTS + 3 * oi + 2] = __saturatef(b0 * inv);
        }
        if (ok1) {
            int oi = __float_as_int(pb.w);
            float inv = 1.0f / (1.0f + 1e-6f - w1);
            out[oi] = d1;
            out[NPTS + 3 * oi + 0] = __saturatef(r1 * inv);
            out[NPTS + 3 * oi + 1] = __saturatef(g1 * inv);
            out[NPTS + 3 * oi + 2] = __saturatef(b1 * inv);
        }
    }
}

extern "C" void kernel_launch(void* const* d_in, const int* in_sizes, int n_in,
                              void* d_out, int out_size)
{
    const float* coords = (const float*)d_in[0];
    const float* shape  = (const float*)d_in[1];
    const float* color  = (const float*)d_in[2];
    const float* alpha  = (const float*)d_in[3];
    float* out = (float*)d_out;

    k_hist<<<NPTS / (4 * 256), 256>>>(coords, out, shape, color, alpha);  // 0
    k_scanTasks<<<1, 1024>>>();                                           // 1
    k_scatter<<<NPTS / (4 * 256), 256>>>(coords);                         // 2
    k_cull<<<NC / 8, 256>>>(shape, color, alpha);                         // 3 (ncu probe)
    k_main<<<1184, 128>>>(out);                                           // 4 (persistent)
}

// round 14
// speedup vs baseline: 1.2655x; 1.0935x over previous
#include <cuda_runtime.h>

#define NPTS 2097152
#define NSTK 500
#define G    32
#define NC   (G*G*G)            // 32768 cells
#define WTASK 128               // points per warp-task (4 per thread)
#define MAXT 81920
#define MAXL 192

using ull = unsigned long long;

// ---- packed f32x2 helpers (sm_103a) ----
__device__ __forceinline__ ull pk2(float lo, float hi) {
    ull r; asm("mov.b64 %0, {%1, %2};" : "=l"(r) : "f"(lo), "f"(hi)); return r;
}
__device__ __forceinline__ void up2(ull v, float& a, float& b) {
    asm("mov.b64 {%0, %1}, %2;" : "=f"(a), "=f"(b) : "l"(v));
}
__device__ __forceinline__ ull add2(ull a, ull b) {
    ull r; asm("add.rn.f32x2 %0, %1, %2;" : "=l"(r) : "l"(a), "l"(b)); return r;
}
__device__ __forceinline__ ull mul2(ull a, ull b) {
    ull r; asm("mul.rn.f32x2 %0, %1, %2;" : "=l"(r) : "l"(a), "l"(b)); return r;
}
__device__ __forceinline__ ull fma2(ull a, ull b, ull c) {
    ull r; asm("fma.rn.f32x2 %0, %1, %2, %3;" : "=l"(r) : "l"(a), "l"(b), "l"(c)); return r;
}
__device__ __forceinline__ float sqapx(float x) {
    float r; asm("sqrt.approx.f32 %0, %1;" : "=f"(r) : "f"(x)); return r;
}

#define ONE2   0x3f8000003f800000ull
#define NEG12  0xbf800000bf800000ull

// ---- scratch (device globals; zero-initialized at load) ----
__device__ float4      g_sorted[NPTS];       // wx,wy,wz, origidx-as-bits
__device__ unsigned    g_pack[NPTS];         // (cell<<17) | within-cell rank
__device__ int         g_hist[NC];           // INVARIANT: zero at entry to k_hist
__device__ int         g_off[NC];
__device__ int         g_cellCnt[NC];
__device__ float4      g_init4[NC];          // truncation init (d, r, g, b)
__device__ float       g_initw[NC];          // truncation init weight (0 or 1)
__device__ int         g_cellList[NC * MAXL];// contiguous per cell: [c*MAXL + j]
__device__ ulonglong2  g_spk[NSTK * 4];      // packed stroke params
__device__ int4        g_tasks[MAXT];
__device__ int         g_taskCount;
__device__ int         g_fetch;

__device__ __forceinline__ int cellOf(float x, float y, float z) {
    int ix = min(max(__float2int_rd((x + 1.0f) * 16.0f), 0), G - 1);
    int iy = min(max(__float2int_rd((y + 1.0f) * 16.0f), 0), G - 1);
    int iz = min(max(__float2int_rd((z + 1.0f) * 16.0f), 0), G - 1);
    return ix | (iy << 5) | (iz << 10);
}

__device__ __forceinline__ void warp_pt(float x, float y, float z,
                                        float& wx, float& wy, float& wz) {
    float n2 = fmaf(x, x, fmaf(y, y, z * z));
    float n  = fmaxf(sqrtf(n2), 1e-9f);
    float sc = 0.5f;
    if (n > 1.0f) sc = (2.0f - 1.0f / n) / n * 0.5f;
    wx = x * sc; wy = y * sc; wz = z * sc;
}

// ---------- L0: warp coords, emit coord output, histogram + rank; pack strokes ----------
__global__ void __launch_bounds__(256)
k_hist(const float* __restrict__ coords, float* __restrict__ out,
       const float* __restrict__ shape, const float* __restrict__ color,
       const float* __restrict__ alpha) {
    const int t = blockIdx.x * blockDim.x + threadIdx.x;
    if (t == 0) { g_taskCount = 0; g_fetch = 0; }
    if (t < NSTK) {
        int s = t;
        float cx = shape[4 * s + 0], cy = shape[4 * s + 1];
        float cz = shape[4 * s + 2], r = shape[4 * s + 3];
        float A  = fmaf(5.0f, r, 0.5f);
        float B2 = (A * 0.2f) * (A * 0.2f);
        float d  = fmaxf(alpha[s], 0.0f) * 50.0f;
        float cr = color[3 * s + 0], cg = color[3 * s + 1], cb = color[3 * s + 2];
        g_spk[4 * s + 0] = make_ulonglong2(pk2(-cx, -cx), pk2(-cy, -cy));
        g_spk[4 * s + 1] = make_ulonglong2(pk2(-cz, -cz), pk2(A, B2));
        g_spk[4 * s + 2] = make_ulonglong2(pk2(d, d),     pk2(cr, cr));
        g_spk[4 * s + 3] = make_ulonglong2(pk2(cg, cg),   pk2(cb, cb));
    }
    const float4* c4 = (const float4*)coords;
    float4 a = c4[3 * t + 0], b = c4[3 * t + 1], c = c4[3 * t + 2];
    float px[4] = { a.x, a.w, b.z, c.y };
    float py[4] = { a.y, b.x, b.w, c.z };
    float pz[4] = { a.z, b.y, c.x, c.w };
    float wxo[4], wyo[4], wzo[4];
#pragma unroll
    for (int i = 0; i < 4; i++) {
        warp_pt(px[i], py[i], pz[i], wxo[i], wyo[i], wzo[i]);
        int cc = cellOf(wxo[i], wyo[i], wzo[i]);
        unsigned rank = (unsigned)atomicAdd(&g_hist[cc], 1);
        g_pack[4 * t + i] = ((unsigned)cc << 17) | rank;
    }
    float4* o4 = (float4*)(out + 4 * NPTS);
    o4[3 * t + 0] = make_float4(wxo[0], wyo[0], wzo[0], wxo[1]);
    o4[3 * t + 1] = make_float4(wyo[1], wzo[1], wxo[2], wyo[2]);
    o4[3 * t + 2] = make_float4(wzo[2], wxo[3], wyo[3], wzo[3]);
}

// ---------- L1: scan over 32768 cells + warp-task building; re-zeros g_hist ----------
__global__ void __launch_bounds__(1024, 1)
k_scanTasks() {
    __shared__ int warpsum[32];
    int tid = threadIdx.x;
    int lane = tid & 31, wid = tid >> 5;
    int base = tid * 32;
    int v[32];
    int s = 0;
#pragma unroll
    for (int k = 0; k < 32; k++) { v[k] = g_hist[base + k]; s += v[k]; }
#pragma unroll
    for (int k = 0; k < 32; k++) g_hist[base + k] = 0;   // restore invariant
    int ps = s;
#pragma unroll
    for (int off = 1; off < 32; off <<= 1) {
        int t = __shfl_up_sync(0xffffffff, ps, off);
        if (lane >= off) ps += t;
    }
    if (lane == 31) warpsum[wid] = ps;
    __syncthreads();
    if (wid == 0) {
        int w = warpsum[lane];
        int pw = w;
#pragma unroll
        for (int off = 1; off < 32; off <<= 1) {
            int t = __shfl_up_sync(0xffffffff, pw, off);
            if (lane >= off) pw += t;
        }
        warpsum[lane] = pw - w;
    }
    __syncthreads();
    int o = warpsum[wid] + ps - s;
#pragma unroll
    for (int k = 0; k < 32; k++) {
        int c = base + k;
        g_off[c] = o;
        int np = v[k];
        if (np > 0) {
            int nt = (np + WTASK - 1) / WTASK;
            int b = atomicAdd(&g_taskCount, nt);
            for (int q = 0; q < nt; q++) {
                int a = o + q * WTASK;
                int e = min(o + np, a + WTASK);
                g_tasks[b + q] = make_int4(c, a, e, 0);
            }
        }
        o += np;
    }
}

// ---------- L2 (fused): blocks [0,2048): scatter; blocks [2048,6144): warp-per-cell cull ----------
// Disjoint outputs (g_sorted vs g_cellList/g_cellCnt/g_init*), no shared counters -> race-free.
#define SCATBLKS (NPTS / (4 * 256))   // 2048
#define CULLBLKS (NC / 8)             // 4096

__global__ void __launch_bounds__(256)
k_scatcull(const float* __restrict__ coords,
           const float* __restrict__ shape,
           const float* __restrict__ color,
           const float* __restrict__ alpha) {
    if (blockIdx.x < SCATBLKS) {
        const int t = blockIdx.x * blockDim.x + threadIdx.x;
        const float4* c4 = (const float4*)coords;
        float4 a = c4[3 * t + 0], b = c4[3 * t + 1], c = c4[3 * t + 2];
        float px[4] = { a.x, a.w, b.z, c.y };
        float py[4] = { a.y, b.x, b.w, c.z };
        float pz[4] = { a.z, b.y, c.x, c.w };
#pragma unroll
        for (int i = 0; i < 4; i++) {
            float wx, wy, wz;
            warp_pt(px[i], py[i], pz[i], wx, wy, wz);
            unsigned pk = g_pack[4 * t + i];
            int cc   = (int)(pk >> 17);
            int rank = (int)(pk & 0x1FFFFu);
            int pos  = g_off[cc] + rank;
            g_sorted[pos] = make_float4(wx, wy, wz, __int_as_float(4 * t + i));
        }
    } else {
        const int c    = ((blockIdx.x - SCATBLKS) * blockDim.x + threadIdx.x) >> 5;
        const int lane = threadIdx.x & 31;

        int ix = c & 31, iy = (c >> 5) & 31, iz = c >> 10;
        const float cs = 0.0625f;
        float lox = -1.0f + ix * cs, hix = lox + cs;
        float loy = -1.0f + iy * cs, hiy = loy + cs;
        float loz = -1.0f + iz * cs, hiz = loz + cs;

        int cnt = 0;
        int lastFull = -1;
        int* __restrict__ myList = &g_cellList[c * MAXL];

        for (int base = 0; base < NSTK; base += 32) {
            int s = base + lane;
            bool hit = false, full = false;
            if (s < NSTK) {
                float4 sp = *(const float4*)&shape[4 * s];
                float R = sp.w + 0.1f + 1e-4f;
                float dx = fmaxf(fmaxf(lox - sp.x, sp.x - hix), 0.0f);
                float dy = fmaxf(fmaxf(loy - sp.y, sp.y - hiy), 0.0f);
                float dz = fmaxf(fmaxf(loz - sp.z, sp.z - hiz), 0.0f);
                float d2 = fmaf(dx, dx, fmaf(dy, dy, dz * dz));
                if (d2 < R * R) {
                    hit = true;
                    float fx = fmaxf(sp.x - lox, hix - sp.x);
                    float fy = fmaxf(sp.y - loy, hiy - sp.y);
                    float fz = fmaxf(sp.z - loz, hiz - sp.z);
                    float f2 = fmaf(fx, fx, fmaf(fy, fy, fz * fz));
                    float Rin = sp.w - 0.1f - 1e-3f;
                    full = (Rin > 0.0f) && (f2 < Rin * Rin);
                }
            }
            unsigned hm = __ballot_sync(0xffffffffu, hit);
            unsigned fm = __ballot_sync(0xffffffffu, full);
            unsigned append = hm & ~fm;
            if (fm) {
                int f = 31 - __clz(fm);
                lastFull = base + f;
                cnt = 0;
                append &= (0xFFFFFFFEu << f);
            }
            if (append & (1u << lane)) {
                int pos = cnt + __popc(append & ((1u << lane) - 1));
                if (pos < MAXL) myList[pos] = s;
            }
            cnt = min(cnt + __popc(append), MAXL);
        }

        if (lane == 0) {
            g_cellCnt[c] = cnt;
            if (lastFull >= 0) {
                int s = lastFull;
                g_init4[c] = make_float4(fmaxf(alpha[s], 0.0f) * 50.0f,
                                         color[3 * s + 0], color[3 * s + 1], color[3 * s + 2]);
                g_initw[c] = 0.0f;
            } else {
                g_init4[c] = make_float4(0.f, 0.f, 0.f, 0.f);
                g_initw[c] = 1.0f;
            }
        }
    }
}

// ---------- L3: persistent main blend, 4 pts/thread (2 packed pairs) ----------
__global__ void __launch_bounds__(128)
k_main(float* __restrict__ out) {
    const int lane = threadIdx.x & 31;
    const int nTasks = g_taskCount;

    for (;;) {
        int tkid;
        if (lane == 0) tkid = atomicAdd(&g_fetch, 1);
        tkid = __shfl_sync(0xffffffffu, tkid, 0);
        if (tkid >= nTasks) return;
        int4 tk = g_tasks[tkid];
        const int cell = tk.x, start = tk.y, end = tk.z;
        const int m = g_cellCnt[cell];
        const int* __restrict__ list = &g_cellList[cell * MAXL];

        const int p0 = start + lane * 4;
        bool ok[4];
        float4 pt[4];
#pragma unroll
        for (int i = 0; i < 4; i++) {
            ok[i] = (p0 + i) < end;
            pt[i] = ok[i] ? g_sorted[p0 + i] : make_float4(9.f, 9.f, 9.f, 0.f);
        }

        ull cxx[2] = { pk2(pt[0].x, pt[1].x), pk2(pt[2].x, pt[3].x) };
        ull cyy[2] = { pk2(pt[0].y, pt[1].y), pk2(pt[2].y, pt[3].y) };
        ull czz[2] = { pk2(pt[0].z, pt[1].z), pk2(pt[2].z, pt[3].z) };

        float4 iv = g_init4[cell];
        float  iw = g_initw[cell];
        ull hd[2] = { pk2(iv.x, iv.x), pk2(iv.x, iv.x) };
        ull hr[2] = { pk2(iv.y, iv.y), pk2(iv.y, iv.y) };
        ull hg[2] = { pk2(iv.z, iv.z), pk2(iv.z, iv.z) };
        ull hb[2] = { pk2(iv.w, iv.w), pk2(iv.w, iv.w) };
        ull hw[2] = { pk2(iw, iw),     pk2(iw, iw) };

        // software-pipelined: prefetch next stroke while blending current
        ulonglong2 v0, v1, v2, v3;
        if (m > 0) {
            int s = list[0];
            v0 = g_spk[4 * s + 0]; v1 = g_spk[4 * s + 1];
            v2 = g_spk[4 * s + 2]; v3 = g_spk[4 * s + 3];
        }
        for (int j = 0; j < m; j++) {
            ulonglong2 n0, n1, n2, n3;
            if (j + 1 < m) {
                int s = list[j + 1];
                n0 = g_spk[4 * s + 0]; n1 = g_spk[4 * s + 1];
                n2 = g_spk[4 * s + 2]; n3 = g_spk[4 * s + 3];
            }
            float A, B2; up2(v1.y, A, B2);
            ull d2p[2];
#pragma unroll
            for (int p = 0; p < 2; p++) {
                ull dx = add2(cxx[p], v0.x);
                ull dy = add2(cyy[p], v0.y);
                ull dz = add2(czz[p], v1.x);
                ull d2 = mul2(dx, dx);
                d2 = fma2(dy, dy, d2);
                d2p[p] = fma2(dz, dz, d2);
            }
            float qa, qb, qc, qd;
            up2(d2p[0], qa, qb);
            up2(d2p[1], qc, qd);
            bool act = (qa < B2) | (qb < B2) | (qc < B2) | (qd < B2);
            if (__ballot_sync(0xffffffffu, act)) {
                float t0 = __saturatef(fmaf(sqapx(qa), -5.0f, A));
                float t1 = __saturatef(fmaf(sqapx(qb), -5.0f, A));
                float t2_ = __saturatef(fmaf(sqapx(qc), -5.0f, A));
                float t3 = __saturatef(fmaf(sqapx(qd), -5.0f, A));
                ull tp[2] = { pk2(t0, t1), pk2(t2_, t3) };
#pragma unroll
                for (int p = 0; p < 2; p++) {
                    ull t2 = tp[p];
                    ull omt = fma2(t2, NEG12, ONE2);
                    hd[p] = fma2(t2, v2.x, mul2(omt, hd[p]));
                    hr[p] = fma2(t2, v2.y, mul2(omt, hr[p]));
                    hg[p] = fma2(t2, v3.x, mul2(omt, hg[p]));
                    hb[p] = fma2(t2, v3.y, mul2(omt, hb[p]));
                    hw[p] = mul2(omt, hw[p]);
                }
            }
            v0 = n0; v1 = n1; v2 = n2; v3 = n3;
        }

#pragma unroll
        for (int p = 0; p < 2; p++) {
            float d0, d1, w0, w1, r0, r1, g0, g1, b0, b1;
            up2(hd[p], d0, d1);
            up2(hw[p], w0, w1);
            up2(hr[p], r0, r1);
            up2(hg[p], g0, g1);
            up2(hb[p], b0, b1);
            float dv[2] = { d0, d1 }, wv[2] = { w0, w1 };
            float rv[2] = { r0, r1 }, gv[2] = { g0, g1 }, bv[2] = { b0, b1 };
#pragma unroll
            for (int q = 0; q < 2; q++) {
                int i = 2 * p + q;
                if (ok[i]) {
                    int oi = __float_as_int(pt[i].w);
                    float inv = 1.0f / (1.0f + 1e-6f - wv[q]);
                    out[oi] = dv[q];
                    out[NPTS + 3 * oi + 0] = __saturatef(rv[q] * inv);
                    out[NPTS + 3 * oi + 1] = __saturatef(gv[q] * inv);
                    out[NPTS + 3 * oi + 2] = __saturatef(bv[q] * inv);
                }
            }
        }
    }
}

extern "C" void kernel_launch(void* const* d_in, const int* in_sizes, int n_in,
                              void* d_out, int out_size)
{
    const float* coords = (const float*)d_in[0];
    const float* shape  = (const float*)d_in[1];
    const float* color  = (const float*)d_in[2];
    const float* alpha  = (const float*)d_in[3];
    float* out = (float*)d_out;

    k_hist<<<NPTS / (4 * 256), 256>>>(coords, out, shape, color, alpha);      // 0
    k_scanTasks<<<1, 1024>>>();                                               // 1
    k_scatcull<<<SCATBLKS + CULLBLKS, 256>>>(coords, shape, color, alpha);    // 2
    k_main<<<1184, 128>>>(out);                                               // 3 (ncu probe)
}